// round 2
// baseline (speedup 1.0000x reference)
#include <cuda_runtime.h>
#include <math.h>

#define B_   16
#define SQ_  128
#define SV_  128
#define DQ_  512
#define DV_  512
#define U_   256
#define CTX_ELEMS (B_*SQ_*DV_)   // context first, weights after

typedef unsigned long long ull;

// Scratch (allocation-free rule: __device__ globals)
__device__ float g_s1[B_*SQ_*U_];   // [b][q][u]
__device__ float g_s2[B_*SV_*U_];   // [b][v][u]

__device__ __forceinline__ float tanh_fast(float x) {
    float y;
    asm("tanh.approx.f32 %0, %1;" : "=f"(y) : "f"(x));
    return y;
}
__device__ __forceinline__ ull pack2(float x, float y) {
    ull r;
    asm("mov.b64 %0, {%1, %2};" : "=l"(r)
        : "r"(__float_as_uint(x)), "r"(__float_as_uint(y)));
    return r;
}
__device__ __forceinline__ void ffma2(ull& d, ull a, ull b) {
    asm("fma.rn.f32x2 %0, %1, %2, %0;" : "+l"(d) : "l"(a), "l"(b));
}
__device__ __forceinline__ void addf2(ull& d, ull a) {
    asm("add.rn.f32x2 %0, %0, %1;" : "+l"(d) : "l"(a));
}
__device__ __forceinline__ float2 unpk(ull v) {
    float2 r;
    asm("mov.b64 {%0, %1}, %2;" : "=f"(r.x), "=f"(r.y) : "l"(v));
    return r;
}

// -------------------------------------------------------------------------
// Fused dual GEMM: z=0: g_s1 = query*W1+b1 ; z=1: g_s2 = values*W2+b2
// 64x64x16 tile, 256 threads, 4x4 microtile via FFMA2 (fp32x2).
// A-tile stored in smem PRE-DUPLICATED ({a,a} pairs) so the inner loop has
// no pack MOVs: 3x LDS.128 + 8x FFMA2 per k.
// -------------------------------------------------------------------------
__global__ __launch_bounds__(256) void gemm_bias_kernel(
    const float* __restrict__ query, const float* __restrict__ values,
    const float* __restrict__ W1, const float* __restrict__ b1,
    const float* __restrict__ W2, const float* __restrict__ b2)
{
    __shared__ ull   As2[16][66];   // k-major, value duplicated {a,a}; pad for 16B align
    __shared__ float Ws[16][64];

    const int which = blockIdx.z;
    const float* __restrict__ A    = which ? values : query;
    const float* __restrict__ W    = which ? W2 : W1;
    const float* __restrict__ bias = which ? b2 : b1;
    float* __restrict__ C          = which ? g_s2 : g_s1;

    const int tid  = threadIdx.x;
    const int bm   = blockIdx.y * 64;
    const int bn   = blockIdx.x * 64;
    const int tx   = tid & 15;          // n-dir (4 cols = 2 f32x2 pairs)
    const int ty   = tid >> 4;          // m-dir (4 rows)
    const int arow = tid >> 2;          // 0..63
    const int ak   = (tid & 3) << 2;    // 0,4,8,12
    const int wrow = tid >> 4;          // 0..15
    const int wn   = (tid & 15) << 2;   // 0..60

    const float* Ap = A + (size_t)(bm + arow) * DQ_ + ak;
    const float* Wp = W + (size_t)wrow * U_ + bn + wn;

    float4 ap = *(const float4*)Ap;
    float4 wp = *(const float4*)Wp;

    ull c2[4][2];   // [row][col-pair]
    #pragma unroll
    for (int i = 0; i < 4; i++) { c2[i][0] = 0ull; c2[i][1] = 0ull; }

    #pragma unroll 1
    for (int kt = 0; kt < DQ_/16; ++kt) {
        As2[ak+0][arow] = pack2(ap.x, ap.x);
        As2[ak+1][arow] = pack2(ap.y, ap.y);
        As2[ak+2][arow] = pack2(ap.z, ap.z);
        As2[ak+3][arow] = pack2(ap.w, ap.w);
        *(float4*)&Ws[wrow][wn] = wp;
        __syncthreads();
        if (kt + 1 < DQ_/16) {
            ap = *(const float4*)(Ap + (kt+1)*16);
            wp = *(const float4*)(Wp + (size_t)(kt+1)*16*U_);
        }
        #pragma unroll
        for (int k = 0; k < 16; k++) {
            ulonglong2 a01 = *(const ulonglong2*)&As2[k][ty << 2];
            ulonglong2 a23 = *(const ulonglong2*)&As2[k][(ty << 2) + 2];
            ulonglong2 w01 = *(const ulonglong2*)&Ws[k][tx << 2];
            ffma2(c2[0][0], a01.x, w01.x);  ffma2(c2[0][1], a01.x, w01.y);
            ffma2(c2[1][0], a01.y, w01.x);  ffma2(c2[1][1], a01.y, w01.y);
            ffma2(c2[2][0], a23.x, w01.x);  ffma2(c2[2][1], a23.x, w01.y);
            ffma2(c2[3][0], a23.y, w01.x);  ffma2(c2[3][1], a23.y, w01.y);
        }
        __syncthreads();
    }

    float4 bv = *(const float4*)(bias + bn + (tx << 2));
    #pragma unroll
    for (int i = 0; i < 4; i++) {
        float2 lo = unpk(c2[i][0]);
        float2 hi = unpk(c2[i][1]);
        float4 o;
        o.x = lo.x + bv.x;
        o.y = lo.y + bv.y;
        o.z = hi.x + bv.z;
        o.w = hi.y + bv.w;
        *(float4*)&C[(size_t)(bm + (ty << 2) + i) * U_ + bn + (tx << 2)] = o;
    }
}

// -------------------------------------------------------------------------
// Fused attention: per CTA = (batch b, 16-query tile), 512 threads.
//   score (tanh/MUFU-bound) -> softmax over v -> weights out -> context GEMV
//   (v split in 4 quarters, f32x2 FMA, smem tree-reduce).
// -------------------------------------------------------------------------
#define S2STRIDE 260

__global__ __launch_bounds__(512, 1) void attn_kernel(
    const float* __restrict__ values, const float* __restrict__ Vw,
    float* __restrict__ out)
{
    extern __shared__ float sm[];
    float* s2s = sm;                         // 128*260 = 33280 floats
    float* s1s = sm + 128 * S2STRIDE;        // 16*256  = 4096
    float* vws = s1s + 16 * U_;              // 256
    float* sc  = vws + U_;                   // 16*128  = 2048

    const int tid = threadIdx.x;
    const int b   = blockIdx.x >> 3;
    const int q0  = (blockIdx.x & 7) << 4;

    // --- stage s2[b], s1 tile, Vw into smem ---
    const float4* s2g4 = (const float4*)(g_s2 + (size_t)b * SV_ * U_);
    for (int i = tid; i < SV_ * (U_/4); i += 512) {
        int v = i >> 6, uq = i & 63;
        *(float4*)&s2s[v * S2STRIDE + (uq << 2)] = s2g4[i];
    }
    const float4* s1g4 = (const float4*)(g_s1 + ((size_t)b * SQ_ + q0) * U_);
    for (int i = tid; i < 16 * (U_/4); i += 512)
        ((float4*)s1s)[i] = s1g4[i];
    if (tid < U_/4)
        ((float4*)vws)[tid] = ((const float4*)Vw)[tid];
    __syncthreads();

    // --- scores: score[q][v] = sum_u Vw[u]*tanh(s1[q][u] + s2[v][u]) ---
    {
        const int v  = tid & 127;
        const int qh = tid >> 7;              // 0..3 -> q in [qh*4, qh*4+4)
        float acc[4] = {0, 0, 0, 0};
        const float* s1q = s1s + (qh << 2) * U_;
        const float* s2r = s2s + v * S2STRIDE;
        #pragma unroll 4
        for (int u = 0; u < U_; u += 4) {
            float4 f2 = *(const float4*)(s2r + u);
            float4 wv = *(const float4*)(vws + u);
            #pragma unroll
            for (int qi = 0; qi < 4; qi++) {
                float4 s1v = *(const float4*)(s1q + qi * U_ + u);
                acc[qi] += wv.x * tanh_fast(s1v.x + f2.x)
                         + wv.y * tanh_fast(s1v.y + f2.y)
                         + wv.z * tanh_fast(s1v.z + f2.z)
                         + wv.w * tanh_fast(s1v.w + f2.w);
            }
        }
        #pragma unroll
        for (int qi = 0; qi < 4; qi++)
            sc[((qh << 2) + qi) * SV_ + v] = acc[qi];
    }
    __syncthreads();

    // --- softmax over v; one warp per q row (16 warps) ---
    {
        const int q = tid >> 5, lane = tid & 31;
        float x0 = sc[q*SV_ +      lane];
        float x1 = sc[q*SV_ + 32 + lane];
        float x2 = sc[q*SV_ + 64 + lane];
        float x3 = sc[q*SV_ + 96 + lane];
        float m = fmaxf(fmaxf(x0, x1), fmaxf(x2, x3));
        #pragma unroll
        for (int off = 16; off; off >>= 1)
            m = fmaxf(m, __shfl_xor_sync(0xffffffffu, m, off));
        float e0 = __expf(x0 - m), e1 = __expf(x1 - m);
        float e2 = __expf(x2 - m), e3 = __expf(x3 - m);
        float s = (e0 + e1) + (e2 + e3);
        #pragma unroll
        for (int off = 16; off; off >>= 1)
            s += __shfl_xor_sync(0xffffffffu, s, off);
        float inv = 1.0f / s;
        e0 *= inv; e1 *= inv; e2 *= inv; e3 *= inv;
        sc[q*SV_ +      lane] = e0;
        sc[q*SV_ + 32 + lane] = e1;
        sc[q*SV_ + 64 + lane] = e2;
        sc[q*SV_ + 96 + lane] = e3;
        float* wout = out + CTX_ELEMS + (size_t)(b * SQ_ + q0 + q) * SV_;
        wout[lane]      = e0;
        wout[32 + lane] = e1;
        wout[64 + lane] = e2;
        wout[96 + lane] = e3;
    }
    __syncthreads();

    // --- context[q][d] = sum_v w[q][v] * values[b][v][d]; v split in 4 ---
    {
        const int quarter = tid >> 7;         // v-range quarter (32 v each)
        const int dg      = tid & 127;        // float4 group over DV
        ull acc2[16][2];
        #pragma unroll
        for (int q = 0; q < 16; q++) { acc2[q][0] = 0ull; acc2[q][1] = 0ull; }

        const float* vb  = values + ((size_t)(b * SV_) + (quarter << 5)) * DV_ + (dg << 2);
        const float* scv = sc + (quarter << 5);
        #pragma unroll 4
        for (int vv = 0; vv < 32; vv++) {
            ulonglong2 val2 = *(const ulonglong2*)(vb + (size_t)vv * DV_);
            #pragma unroll
            for (int q = 0; q < 16; q++) {
                float wq = scv[q * SV_ + vv];
                ull wd = pack2(wq, wq);
                ffma2(acc2[q][0], wd, val2.x);
                ffma2(acc2[q][1], wd, val2.y);
            }
        }
        // tree-reduce across quarters in smem (reuse s2s region, done with it)
        ull* cb = (ull*)s2s;  // per-quarter partial: 16q * 128dg * 2 = 4096 ull
        if (quarter) {
            ull* dst = cb + (size_t)(quarter - 1) * 4096;
            #pragma unroll
            for (int q = 0; q < 16; q++)
                *(ulonglong2*)&dst[(q << 8) + (dg << 1)] =
                    make_ulonglong2(acc2[q][0], acc2[q][1]);
        }
        __syncthreads();
        if (quarter == 0) {
            #pragma unroll
            for (int q = 0; q < 16; q++) {
                #pragma unroll
                for (int p = 0; p < 3; p++) {
                    ulonglong2 t = *(const ulonglong2*)
                        &cb[(size_t)p * 4096 + (q << 8) + (dg << 1)];
                    addf2(acc2[q][0], t.x);
                    addf2(acc2[q][1], t.y);
                }
                float2 lo = unpk(acc2[q][0]);
                float2 hi = unpk(acc2[q][1]);
                float4 o = make_float4(lo.x, lo.y, hi.x, hi.y);
                *(float4*)&out[(size_t)(b * SQ_ + q0 + q) * DV_ + (dg << 2)] = o;
            }
        }
    }
}

// -------------------------------------------------------------------------
extern "C" void kernel_launch(void* const* d_in, const int* in_sizes, int n_in,
                              void* d_out, int out_size)
{
    const float* query  = (const float*)d_in[0];
    const float* values = (const float*)d_in[1];
    const float* W1     = (const float*)d_in[2];
    const float* b1     = (const float*)d_in[3];
    const float* W2     = (const float*)d_in[4];
    const float* b2     = (const float*)d_in[5];
    const float* Vw     = (const float*)d_in[6];
    // d_in[7] = Vb: softmax is shift-invariant; score itself is not an
    // output, so Vb provably cancels. Unused.
    float* out = (float*)d_out;

    dim3 gemm_grid(U_/64, (B_*SQ_)/64, 2);          // 4 x 32 x 2 = 256 CTAs
    gemm_bias_kernel<<<gemm_grid, 256>>>(query, values, W1, b1, W2, b2);

    const size_t smbytes =
        (size_t)(128 * S2STRIDE + 16 * U_ + U_ + 16 * SV_) * sizeof(float); // 158720
    cudaFuncSetAttribute(attn_kernel,
                         cudaFuncAttributeMaxDynamicSharedMemorySize,
                         (int)smbytes);
    attn_kernel<<<B_ * 8, 512, smbytes>>>(values, Vw, out);
}

// round 5
// speedup vs baseline: 1.0004x; 1.0004x over previous
#include <cuda_runtime.h>
#include <math.h>

#define B_   16
#define SQ_  128
#define SV_  128
#define DQ_  512
#define DV_  512
#define U_   256
#define CTX_ELEMS (B_*SQ_*DV_)   // context first, weights after

typedef unsigned long long ull;

// Scratch (allocation-free rule: __device__ globals)
__device__ float g_s1[B_*SQ_*U_];   // [b][q][u]
__device__ float g_s2[B_*SV_*U_];   // [b][v][u]

__device__ __forceinline__ float tanh_fast(float x) {
    float y;
    asm("tanh.approx.f32 %0, %1;" : "=f"(y) : "f"(x));
    return y;
}
__device__ __forceinline__ ull pack2(float x, float y) {
    ull r;
    asm("mov.b64 %0, {%1, %2};" : "=l"(r)
        : "r"(__float_as_uint(x)), "r"(__float_as_uint(y)));
    return r;
}
__device__ __forceinline__ void ffma2(ull& d, ull a, ull b) {
    asm("fma.rn.f32x2 %0, %1, %2, %0;" : "+l"(d) : "l"(a), "l"(b));
}
__device__ __forceinline__ float2 unpk(ull v) {
    float2 r;
    asm("mov.b64 {%0, %1}, %2;" : "=f"(r.x), "=f"(r.y) : "l"(v));
    return r;
}

// -------------------------------------------------------------------------
// Fused dual GEMM: z=0: g_s1 = query*W1+b1 ; z=1: g_s2 = values*W2+b2
// 32x64x16 tile, 128 threads, 4x4 microtile via FFMA2.
// 512 CTAs total -> ~3.5 CTAs/SM (14 warps/SM) for latency coverage.
// ASTRIDE=34 ull: row stride 272B (16B-aligned rows, LDS.128-safe),
// inner-loop A-reads are warp broadcasts (conflict-free).
// -------------------------------------------------------------------------
#define ASTRIDE 34

__global__ __launch_bounds__(128) void gemm_bias_kernel(
    const float* __restrict__ query, const float* __restrict__ values,
    const float* __restrict__ W1, const float* __restrict__ b1,
    const float* __restrict__ W2, const float* __restrict__ b2)
{
    __shared__ ull   As2[16][ASTRIDE];  // k-major, values duplicated {a,a}
    __shared__ float Ws[16][64];

    const int which = blockIdx.z;
    const float* __restrict__ A    = which ? values : query;
    const float* __restrict__ W    = which ? W2 : W1;
    const float* __restrict__ bias = which ? b2 : b1;
    float* __restrict__ C          = which ? g_s2 : g_s1;

    const int tid  = threadIdx.x;
    const int bm   = blockIdx.y * 32;
    const int bn   = blockIdx.x * 64;
    const int tx   = tid & 15;          // n-dir: 4 cols (2 f32x2 pairs)
    const int ty   = tid >> 4;          // m-dir: 0..7 -> 4 rows
    const int arow = tid >> 2;          // 0..31
    const int ak   = (tid & 3) << 2;    // 0,4,8,12
    const int wrow = tid >> 4;          // 0..7 (and +8)
    const int wn   = (tid & 15) << 2;   // 0..60

    const float* Ap = A + (size_t)(bm + arow) * DQ_ + ak;
    const float* Wp = W + (size_t)wrow * U_ + bn + wn;

    float4 ap  = *(const float4*)Ap;
    float4 wp0 = *(const float4*)Wp;
    float4 wp1 = *(const float4*)(Wp + 8 * U_);

    ull c2[4][2];   // [row][col-pair]
    #pragma unroll
    for (int i = 0; i < 4; i++) { c2[i][0] = 0ull; c2[i][1] = 0ull; }

    #pragma unroll 1
    for (int kt = 0; kt < DQ_/16; ++kt) {
        As2[ak+0][arow] = pack2(ap.x, ap.x);
        As2[ak+1][arow] = pack2(ap.y, ap.y);
        As2[ak+2][arow] = pack2(ap.z, ap.z);
        As2[ak+3][arow] = pack2(ap.w, ap.w);
        *(float4*)&Ws[wrow][wn]     = wp0;
        *(float4*)&Ws[wrow + 8][wn] = wp1;
        __syncthreads();
        if (kt + 1 < DQ_/16) {
            ap  = *(const float4*)(Ap + (kt+1)*16);
            wp0 = *(const float4*)(Wp + (size_t)(kt+1)*16*U_);
            wp1 = *(const float4*)(Wp + (size_t)((kt+1)*16 + 8)*U_);
        }
        #pragma unroll
        for (int k = 0; k < 16; k++) {
            ulonglong2 a01 = *(const ulonglong2*)&As2[k][ty << 2];
            ulonglong2 a23 = *(const ulonglong2*)&As2[k][(ty << 2) + 2];
            ulonglong2 w01 = *(const ulonglong2*)&Ws[k][tx << 2];
            ffma2(c2[0][0], a01.x, w01.x);  ffma2(c2[0][1], a01.x, w01.y);
            ffma2(c2[1][0], a01.y, w01.x);  ffma2(c2[1][1], a01.y, w01.y);
            ffma2(c2[2][0], a23.x, w01.x);  ffma2(c2[2][1], a23.x, w01.y);
            ffma2(c2[3][0], a23.y, w01.x);  ffma2(c2[3][1], a23.y, w01.y);
        }
        __syncthreads();
    }

    float4 bv = *(const float4*)(bias + bn + (tx << 2));
    #pragma unroll
    for (int i = 0; i < 4; i++) {
        float2 lo = unpk(c2[i][0]);
        float2 hi = unpk(c2[i][1]);
        float4 o;
        o.x = lo.x + bv.x;
        o.y = lo.y + bv.y;
        o.z = hi.x + bv.z;
        o.w = hi.y + bv.w;
        *(float4*)&C[(size_t)(bm + (ty << 2) + i) * U_ + bn + (tx << 2)] = o;
    }
}

// -------------------------------------------------------------------------
// Fused attention (R1 layout — measured ~22us): per CTA = (b, 16-q tile),
// 256 threads. score (MUFU-bound) -> softmax -> weights out -> context GEMV.
// -------------------------------------------------------------------------
#define S2STRIDE 260

__global__ __launch_bounds__(256, 1) void attn_kernel(
    const float* __restrict__ values, const float* __restrict__ Vw,
    float* __restrict__ out)
{
    extern __shared__ float sm[];
    float* s2s = sm;                         // 128*260 = 33280 floats
    float* s1s = sm + 128 * S2STRIDE;        // 16*256  = 4096
    float* vws = s1s + 16 * U_;              // 256
    float* sc  = vws + U_;                   // 16*128  = 2048

    const int tid = threadIdx.x;
    const int b   = blockIdx.x >> 3;
    const int q0  = (blockIdx.x & 7) << 4;

    // --- stage s2[b], s1 tile, Vw into smem ---
    const float4* s2g4 = (const float4*)(g_s2 + (size_t)b * SV_ * U_);
    for (int i = tid; i < SV_ * (U_/4); i += 256) {
        int v = i >> 6, uq = i & 63;
        *(float4*)&s2s[v * S2STRIDE + (uq << 2)] = s2g4[i];
    }
    const float4* s1g4 = (const float4*)(g_s1 + ((size_t)b * SQ_ + q0) * U_);
    for (int i = tid; i < 16 * (U_/4); i += 256)
        ((float4*)s1s)[i] = s1g4[i];
    if (tid < U_/4)
        ((float4*)vws)[tid] = ((const float4*)Vw)[tid];
    __syncthreads();

    // --- scores: score[q][v] = sum_u Vw[u]*tanh(s1[q][u] + s2[v][u]) ---
    {
        const int v  = tid & 127;
        const int qh = tid >> 7;              // 0 or 1 -> q in [qh*8, qh*8+8)
        float acc[8] = {0,0,0,0,0,0,0,0};
        const float* s1q = s1s + (qh << 3) * U_;
        const float* s2r = s2s + v * S2STRIDE;
        #pragma unroll 2
        for (int u = 0; u < U_; u += 4) {
            float4 f2 = *(const float4*)(s2r + u);
            float4 wv = *(const float4*)(vws + u);
            #pragma unroll
            for (int qi = 0; qi < 8; qi++) {
                float4 s1v = *(const float4*)(s1q + qi * U_ + u);
                acc[qi] += wv.x * tanh_fast(s1v.x + f2.x)
                         + wv.y * tanh_fast(s1v.y + f2.y)
                         + wv.z * tanh_fast(s1v.z + f2.z)
                         + wv.w * tanh_fast(s1v.w + f2.w);
            }
        }
        #pragma unroll
        for (int qi = 0; qi < 8; qi++)
            sc[((qh << 3) + qi) * SV_ + v] = acc[qi];
    }
    __syncthreads();

    // --- softmax over v; each warp handles 2 q rows ---
    {
        const int w = tid >> 5, lane = tid & 31;
        #pragma unroll
        for (int qq = 0; qq < 2; qq++) {
            int q = (w << 1) + qq;
            float x0 = sc[q*SV_ +      lane];
            float x1 = sc[q*SV_ + 32 + lane];
            float x2 = sc[q*SV_ + 64 + lane];
            float x3 = sc[q*SV_ + 96 + lane];
            float m = fmaxf(fmaxf(x0, x1), fmaxf(x2, x3));
            #pragma unroll
            for (int off = 16; off; off >>= 1)
                m = fmaxf(m, __shfl_xor_sync(0xffffffffu, m, off));
            float e0 = __expf(x0 - m), e1 = __expf(x1 - m);
            float e2 = __expf(x2 - m), e3 = __expf(x3 - m);
            float s = (e0 + e1) + (e2 + e3);
            #pragma unroll
            for (int off = 16; off; off >>= 1)
                s += __shfl_xor_sync(0xffffffffu, s, off);
            float inv = 1.0f / s;
            e0 *= inv; e1 *= inv; e2 *= inv; e3 *= inv;
            sc[q*SV_ +      lane] = e0;
            sc[q*SV_ + 32 + lane] = e1;
            sc[q*SV_ + 64 + lane] = e2;
            sc[q*SV_ + 96 + lane] = e3;
            float* wout = out + CTX_ELEMS + (size_t)(b * SQ_ + q0 + q) * SV_;
            wout[lane]      = e0;
            wout[32 + lane] = e1;
            wout[64 + lane] = e2;
            wout[96 + lane] = e3;
        }
    }
    __syncthreads();

    // --- context[q][d] = sum_v w[q][v] * values[b][v][d]; v split in halves ---
    {
        const int half = tid >> 7;            // v-range half
        const int dg   = tid & 127;           // float4 group over DV
        float4 acc[16];
        #pragma unroll
        for (int q = 0; q < 16; q++) acc[q] = make_float4(0.f, 0.f, 0.f, 0.f);

        const float* vb  = values + ((size_t)(b * SV_) + (half << 6)) * DV_ + (dg << 2);
        const float* scv = sc + (half << 6);
        #pragma unroll 4
        for (int vv = 0; vv < 64; vv++) {
            float4 val = *(const float4*)(vb + (size_t)vv * DV_);
            #pragma unroll
            for (int q = 0; q < 16; q++) {
                float wq = scv[q * SV_ + vv];
                acc[q].x += wq * val.x;
                acc[q].y += wq * val.y;
                acc[q].z += wq * val.z;
                acc[q].w += wq * val.w;
            }
        }
        float4* cbuf = (float4*)s2s;   // reuse s2 smem region (done with it)
        if (half) {
            #pragma unroll
            for (int q = 0; q < 16; q++) cbuf[q * 128 + dg] = acc[q];
        }
        __syncthreads();
        if (!half) {
            #pragma unroll
            for (int q = 0; q < 16; q++) {
                float4 o = cbuf[q * 128 + dg];
                o.x += acc[q].x; o.y += acc[q].y;
                o.z += acc[q].z; o.w += acc[q].w;
                *(float4*)&out[(size_t)(b * SQ_ + q0 + q) * DV_ + (dg << 2)] = o;
            }
        }
    }
}

// -------------------------------------------------------------------------
extern "C" void kernel_launch(void* const* d_in, const int* in_sizes, int n_in,
                              void* d_out, int out_size)
{
    const float* query  = (const float*)d_in[0];
    const float* values = (const float*)d_in[1];
    const float* W1     = (const float*)d_in[2];
    const float* b1     = (const float*)d_in[3];
    const float* W2     = (const float*)d_in[4];
    const float* b2     = (const float*)d_in[5];
    const float* Vw     = (const float*)d_in[6];
    // d_in[7] = Vb: softmax is shift-invariant; score itself is not an
    // output, so Vb provably cancels. Unused.
    float* out = (float*)d_out;

    dim3 gemm_grid(U_/64, (B_*SQ_)/32, 2);          // 4 x 64 x 2 = 512 CTAs
    gemm_bias_kernel<<<gemm_grid, 128>>>(query, values, W1, b1, W2, b2);

    const size_t smbytes =
        (size_t)(128 * S2STRIDE + 16 * U_ + U_ + 16 * SV_) * sizeof(float); // 158720
    cudaFuncSetAttribute(attn_kernel,
                         cudaFuncAttributeMaxDynamicSharedMemorySize,
                         (int)smbytes);
    attn_kernel<<<B_ * 8, 256, smbytes>>>(values, Vw, out);
}

// round 6
// speedup vs baseline: 1.1809x; 1.1805x over previous
#include <cuda_runtime.h>
#include <math.h>

#define B_   16
#define SQ_  128
#define SV_  128
#define DQ_  512
#define DV_  512
#define U_   256
#define CTX_ELEMS (B_*SQ_*DV_)   // context first, weights after

// Scratch (allocation-free rule: __device__ globals)
__device__ float g_s1[B_*SQ_*U_];   // [b][q][u]
__device__ float g_s2[B_*SV_*U_];   // [b][v][u]

__device__ __forceinline__ float tanh_fast(float x) {
    float y;
    asm("tanh.approx.f32 %0, %1;" : "=f"(y) : "f"(x));
    return y;
}

// -------------------------------------------------------------------------
// Fused dual scalar GEMM: z=0: g_s1 = query*W1+b1 ; z=1: g_s2 = values*W2+b2
// 64x64x16 tile, 256 threads, 4x4 scalar microtile, double-buffered smem
// (one __syncthreads per k-tile). 256 CTAs -> ~2 CTAs/SM.
// -------------------------------------------------------------------------
__global__ __launch_bounds__(256) void gemm_bias_kernel(
    const float* __restrict__ query, const float* __restrict__ values,
    const float* __restrict__ W1, const float* __restrict__ b1,
    const float* __restrict__ W2, const float* __restrict__ b2)
{
    __shared__ float As[2][16][68];   // k-major A tile (padded)
    __shared__ float Ws[2][16][64];

    const int which = blockIdx.z;
    const float* __restrict__ A    = which ? values : query;
    const float* __restrict__ W    = which ? W2 : W1;
    const float* __restrict__ bias = which ? b2 : b1;
    float* __restrict__ C          = which ? g_s2 : g_s1;

    const int tid  = threadIdx.x;
    const int bm   = blockIdx.y * 64;
    const int bn   = blockIdx.x * 64;
    const int tx   = tid & 15;          // n-dir
    const int ty   = tid >> 4;          // m-dir
    const int arow = tid >> 2;          // 0..63
    const int ak   = (tid & 3) << 2;    // 0,4,8,12
    const int wrow = tid >> 4;          // 0..15
    const int wn   = (tid & 15) << 2;   // 0..60

    const float* Ap = A + (size_t)(bm + arow) * DQ_ + ak;
    const float* Wp = W + (size_t)wrow * U_ + bn + wn;

    float4 ap = *(const float4*)Ap;
    float4 wp = *(const float4*)Wp;

    float c[4][4];
    #pragma unroll
    for (int i = 0; i < 4; i++)
        #pragma unroll
        for (int j = 0; j < 4; j++) c[i][j] = 0.f;

    // prologue: fill buffer 0
    As[0][ak+0][arow] = ap.x;
    As[0][ak+1][arow] = ap.y;
    As[0][ak+2][arow] = ap.z;
    As[0][ak+3][arow] = ap.w;
    *(float4*)&Ws[0][wrow][wn] = wp;
    __syncthreads();

    #pragma unroll 1
    for (int kt = 0; kt < DQ_/16; ++kt) {
        const int cur = kt & 1;
        const int nxt = cur ^ 1;
        if (kt + 1 < DQ_/16) {
            ap = *(const float4*)(Ap + (kt+1)*16);
            wp = *(const float4*)(Wp + (size_t)(kt+1)*16*U_);
        }
        #pragma unroll
        for (int k = 0; k < 16; k++) {
            float4 a4 = *(const float4*)&As[cur][k][ty << 2];
            float4 w4 = *(const float4*)&Ws[cur][k][tx << 2];
            float av[4] = {a4.x, a4.y, a4.z, a4.w};
            float wv[4] = {w4.x, w4.y, w4.z, w4.w};
            #pragma unroll
            for (int i = 0; i < 4; i++)
                #pragma unroll
                for (int j = 0; j < 4; j++)
                    c[i][j] += av[i] * wv[j];
        }
        if (kt + 1 < DQ_/16) {
            As[nxt][ak+0][arow] = ap.x;
            As[nxt][ak+1][arow] = ap.y;
            As[nxt][ak+2][arow] = ap.z;
            As[nxt][ak+3][arow] = ap.w;
            *(float4*)&Ws[nxt][wrow][wn] = wp;
            __syncthreads();
        }
    }

    float4 bv = *(const float4*)(bias + bn + (tx << 2));
    float bb[4] = {bv.x, bv.y, bv.z, bv.w};
    #pragma unroll
    for (int i = 0; i < 4; i++) {
        float4 o;
        o.x = c[i][0] + bb[0];
        o.y = c[i][1] + bb[1];
        o.z = c[i][2] + bb[2];
        o.w = c[i][3] + bb[3];
        *(float4*)&C[(size_t)(bm + (ty << 2) + i) * U_ + bn + (tx << 2)] = o;
    }
}

// -------------------------------------------------------------------------
// Fused attention (R1 layout, unchanged): per CTA = (b, 16-q tile),
// 256 threads. score (MUFU-bound) -> softmax -> weights out -> context GEMV.
// -------------------------------------------------------------------------
#define S2STRIDE 260

__global__ __launch_bounds__(256, 1) void attn_kernel(
    const float* __restrict__ values, const float* __restrict__ Vw,
    float* __restrict__ out)
{
    extern __shared__ float sm[];
    float* s2s = sm;                         // 128*260 = 33280 floats
    float* s1s = sm + 128 * S2STRIDE;        // 16*256  = 4096
    float* vws = s1s + 16 * U_;              // 256
    float* sc  = vws + U_;                   // 16*128  = 2048

    const int tid = threadIdx.x;
    const int b   = blockIdx.x >> 3;
    const int q0  = (blockIdx.x & 7) << 4;

    // --- stage s2[b], s1 tile, Vw into smem ---
    const float4* s2g4 = (const float4*)(g_s2 + (size_t)b * SV_ * U_);
    for (int i = tid; i < SV_ * (U_/4); i += 256) {
        int v = i >> 6, uq = i & 63;
        *(float4*)&s2s[v * S2STRIDE + (uq << 2)] = s2g4[i];
    }
    const float4* s1g4 = (const float4*)(g_s1 + ((size_t)b * SQ_ + q0) * U_);
    for (int i = tid; i < 16 * (U_/4); i += 256)
        ((float4*)s1s)[i] = s1g4[i];
    if (tid < U_/4)
        ((float4*)vws)[tid] = ((const float4*)Vw)[tid];
    __syncthreads();

    // --- scores: score[q][v] = sum_u Vw[u]*tanh(s1[q][u] + s2[v][u]) ---
    {
        const int v  = tid & 127;
        const int qh = tid >> 7;              // 0 or 1 -> q in [qh*8, qh*8+8)
        float acc[8] = {0,0,0,0,0,0,0,0};
        const float* s1q = s1s + (qh << 3) * U_;
        const float* s2r = s2s + v * S2STRIDE;
        #pragma unroll 2
        for (int u = 0; u < U_; u += 4) {
            float4 f2 = *(const float4*)(s2r + u);
            float4 wv = *(const float4*)(vws + u);
            #pragma unroll
            for (int qi = 0; qi < 8; qi++) {
                float4 s1v = *(const float4*)(s1q + qi * U_ + u);
                acc[qi] += wv.x * tanh_fast(s1v.x + f2.x)
                         + wv.y * tanh_fast(s1v.y + f2.y)
                         + wv.z * tanh_fast(s1v.z + f2.z)
                         + wv.w * tanh_fast(s1v.w + f2.w);
            }
        }
        #pragma unroll
        for (int qi = 0; qi < 8; qi++)
            sc[((qh << 3) + qi) * SV_ + v] = acc[qi];
    }
    __syncthreads();

    // --- softmax over v; each warp handles 2 q rows ---
    {
        const int w = tid >> 5, lane = tid & 31;
        #pragma unroll
        for (int qq = 0; qq < 2; qq++) {
            int q = (w << 1) + qq;
            float x0 = sc[q*SV_ +      lane];
            float x1 = sc[q*SV_ + 32 + lane];
            float x2 = sc[q*SV_ + 64 + lane];
            float x3 = sc[q*SV_ + 96 + lane];
            float m = fmaxf(fmaxf(x0, x1), fmaxf(x2, x3));
            #pragma unroll
            for (int off = 16; off; off >>= 1)
                m = fmaxf(m, __shfl_xor_sync(0xffffffffu, m, off));
            float e0 = __expf(x0 - m), e1 = __expf(x1 - m);
            float e2 = __expf(x2 - m), e3 = __expf(x3 - m);
            float s = (e0 + e1) + (e2 + e3);
            #pragma unroll
            for (int off = 16; off; off >>= 1)
                s += __shfl_xor_sync(0xffffffffu, s, off);
            float inv = 1.0f / s;
            e0 *= inv; e1 *= inv; e2 *= inv; e3 *= inv;
            sc[q*SV_ +      lane] = e0;
            sc[q*SV_ + 32 + lane] = e1;
            sc[q*SV_ + 64 + lane] = e2;
            sc[q*SV_ + 96 + lane] = e3;
            float* wout = out + CTX_ELEMS + (size_t)(b * SQ_ + q0 + q) * SV_;
            wout[lane]      = e0;
            wout[32 + lane] = e1;
            wout[64 + lane] = e2;
            wout[96 + lane] = e3;
        }
    }
    __syncthreads();

    // --- context[q][d] = sum_v w[q][v] * values[b][v][d]; v split in halves ---
    {
        const int half = tid >> 7;            // v-range half
        const int dg   = tid & 127;           // float4 group over DV
        float4 acc[16];
        #pragma unroll
        for (int q = 0; q < 16; q++) acc[q] = make_float4(0.f, 0.f, 0.f, 0.f);

        const float* vb  = values + ((size_t)(b * SV_) + (half << 6)) * DV_ + (dg << 2);
        const float* scv = sc + (half << 6);
        #pragma unroll 4
        for (int vv = 0; vv < 64; vv++) {
            float4 val = *(const float4*)(vb + (size_t)vv * DV_);
            #pragma unroll
            for (int q = 0; q < 16; q++) {
                float wq = scv[q * SV_ + vv];
                acc[q].x += wq * val.x;
                acc[q].y += wq * val.y;
                acc[q].z += wq * val.z;
                acc[q].w += wq * val.w;
            }
        }
        float4* cbuf = (float4*)s2s;   // reuse s2 smem region (done with it)
        if (half) {
            #pragma unroll
            for (int q = 0; q < 16; q++) cbuf[q * 128 + dg] = acc[q];
        }
        __syncthreads();
        if (!half) {
            #pragma unroll
            for (int q = 0; q < 16; q++) {
                float4 o = cbuf[q * 128 + dg];
                o.x += acc[q].x; o.y += acc[q].y;
                o.z += acc[q].z; o.w += acc[q].w;
                *(float4*)&out[(size_t)(b * SQ_ + q0 + q) * DV_ + (dg << 2)] = o;
            }
        }
    }
}

// -------------------------------------------------------------------------
extern "C" void kernel_launch(void* const* d_in, const int* in_sizes, int n_in,
                              void* d_out, int out_size)
{
    const float* query  = (const float*)d_in[0];
    const float* values = (const float*)d_in[1];
    const float* W1     = (const float*)d_in[2];
    const float* b1     = (const float*)d_in[3];
    const float* W2     = (const float*)d_in[4];
    const float* b2     = (const float*)d_in[5];
    const float* Vw     = (const float*)d_in[6];
    // d_in[7] = Vb: softmax is shift-invariant; score itself is not an
    // output, so Vb provably cancels. Unused.
    float* out = (float*)d_out;

    dim3 gemm_grid(U_/64, (B_*SQ_)/64, 2);          // 4 x 32 x 2 = 256 CTAs
    gemm_bias_kernel<<<gemm_grid, 256>>>(query, values, W1, b1, W2, b2);

    const size_t smbytes =
        (size_t)(128 * S2STRIDE + 16 * U_ + U_ + 16 * SV_) * sizeof(float); // 158720
    cudaFuncSetAttribute(attn_kernel,
                         cudaFuncAttributeMaxDynamicSharedMemorySize,
                         (int)smbytes);
    attn_kernel<<<B_ * 8, 256, smbytes>>>(values, Vw, out);
}